// round 13
// baseline (speedup 1.0000x reference)
#include <cuda_runtime.h>
#include <cuda_fp16.h>
#include <math.h>
#include <stdint.h>

// ---------------- problem constants ----------------
#define BATCH 4
#define SEQ   2048
#define CDIM  1024
#define NH    16
#define NHKV  4
#define HD    64
#define TOK   (BATCH*SEQ)          // 8192
#define GKW   512                  // K dim in half2 words (1024 halves)
#define NQKV  1536                 // 1024 + 256 + 256

// fixed softmax max (log2 domain): scores*log2e - 6*log2e
#define FMAXL2 8.656170245333781f  // 6 * log2(e)

// ---------------- scratch (device globals) ----------------
__device__ uint32_t g_xh  [TOK*GKW];         // x as half2 words
__device__ float    g_qkv [TOK*NQKV];        // fused qkv projection (fp32)
__device__ __half   g_qh [BATCH*NH*SEQ*HD];  // q half, scale folded (1.5/8*log2e)
__device__ __half   g_kh [BATCH*NHKV*SEQ*HD];// k half [b,hkv][n][d]
__device__ __half   g_vt [BATCH*NHKV*HD*SEQ];// v half transposed [b,hkv][d][n]
__device__ uint32_t g_y  [TOK*GKW];          // attention out, half2 words
__device__ uint32_t g_wqkvT[NQKV*GKW];       // [N,K] transposed weights half2
__device__ uint32_t g_woT  [CDIM*GKW];

// ---------------- helpers ----------------
__device__ __forceinline__ uint32_t smem_u32(const void* p) {
    uint32_t a;
    asm("{ .reg .u64 t; cvta.to.shared.u64 t, %1; cvt.u32.u64 %0, t; }" : "=r"(a) : "l"(p));
    return a;
}
__device__ __forceinline__ uint32_t f2h2(float lo, float hi) {
    __half2 h = __floats2half2_rn(lo, hi);
    return *(uint32_t*)&h;
}
__device__ __forceinline__ float ex2f(float x) {
    float y;
    asm("ex2.approx.f32 %0, %1;" : "=f"(y) : "f"(x));
    return y;
}
__device__ __forceinline__ void mma_f16(float& d0, float& d1, float& d2, float& d3,
                                        uint32_t a0, uint32_t a1, uint32_t a2, uint32_t a3,
                                        uint32_t b0, uint32_t b1) {
    asm volatile(
        "mma.sync.aligned.m16n8k16.row.col.f32.f16.f16.f32 "
        "{%0,%1,%2,%3}, {%4,%5,%6,%7}, {%8,%9}, {%0,%1,%2,%3};"
        : "+f"(d0), "+f"(d1), "+f"(d2), "+f"(d3)
        : "r"(a0), "r"(a1), "r"(a2), "r"(a3), "r"(b0), "r"(b1));
}
__device__ __forceinline__ void ldsm_x4(uint32_t& r0, uint32_t& r1, uint32_t& r2, uint32_t& r3,
                                        uint32_t addr) {
    asm volatile("ldmatrix.sync.aligned.m8n8.x4.shared.b16 {%0,%1,%2,%3}, [%4];"
                 : "=r"(r0), "=r"(r1), "=r"(r2), "=r"(r3) : "r"(addr));
}
#define CP_ASYNC16(saddr, gptr) \
    asm volatile("cp.async.cg.shared.global [%0], [%1], 16;" :: "r"(saddr), "l"(gptr))
#define CP_COMMIT()  asm volatile("cp.async.commit_group;" ::: "memory")
#define CP_WAIT(n)   asm volatile("cp.async.wait_group %0;" :: "n"(n) : "memory")

// ---------------- x -> half2 words -----------------------------------------
__global__ __launch_bounds__(256) void xconv_kernel(const float* __restrict__ x)
{
    int i = (blockIdx.x * 256 + threadIdx.x) * 4;
    float4 f = *(const float4*)(x + i);
    uint2 u;
    u.x = f2h2(f.x, f.y);
    u.y = f2h2(f.z, f.w);
    *(uint2*)(g_xh + i/2) = u;
}

// ---------------- weight transpose (+half): D[c][r] = h(S[r][c]) -----------
__global__ __launch_bounds__(256) void transpose_kernel(
    const float* __restrict__ S, __half* __restrict__ D, int R, int Ccols)
{
    __shared__ float t[32][33];
    int bx = blockIdx.x * 32, by = blockIdx.y * 32;
#pragma unroll
    for (int i = 0; i < 32; i += 8)
        t[threadIdx.y + i][threadIdx.x] = S[(size_t)(by + threadIdx.y + i) * Ccols + bx + threadIdx.x];
    __syncthreads();
#pragma unroll
    for (int i = 0; i < 32; i += 8)
        D[(size_t)(bx + threadIdx.y + i) * R + by + threadIdx.x] = __float2half(t[threadIdx.x][threadIdx.y + i]);
}

// ---------------- fp16 GEMM, 2-stage double buffer, ldmatrix fragments ------
#define GS   2
#define GBK  32
#define GSTR 36
#define STAGE_W (128*GSTR)
#define GEMM_SMEM (2*GS*STAGE_W*4)     // 73728 B

__global__ __launch_bounds__(256, 2) void mma_gemm_kernel(
    const uint32_t* __restrict__ A, const uint32_t* __restrict__ Bt,
    float* __restrict__ C, int Np)
{
    extern __shared__ uint32_t gsm[];
    uint32_t* As = gsm;
    uint32_t* Bs = gsm + GS*STAGE_W;

    int tid  = threadIdx.x;
    int wid  = tid >> 5, lane = tid & 31;
    int gid  = lane >> 2, tig = lane & 3;
    int wm   = (wid & 1) * 64;
    int wn   = (wid >> 1) * 32;

    int lr = tid >> 1;
    int lc = (tid & 1) * 16;

    const uint32_t* Ag = A  + (size_t)blockIdx.y * 128 * GKW + (size_t)lr * GKW + lc;
    const uint32_t* Bg = Bt + (size_t)blockIdx.x * 128 * GKW + (size_t)lr * GKW + lc;

    uint32_t sA = smem_u32(As) + (uint32_t)(lr * GSTR + lc) * 4u;
    uint32_t sB = smem_u32(Bs) + (uint32_t)(lr * GSTR + lc) * 4u;
    const uint32_t stageB = STAGE_W * 4u;

    int rowa  = (lane & 7) + ((lane >> 3) & 1) * 8;
    int worda = (lane >> 4) * 4;
    int rowb  = (lane & 7) + ((lane >> 4) << 3);
    int wordb = ((lane >> 3) & 1) * 4;
    uint32_t aAddr[4], bAddr[2];
#pragma unroll
    for (int mt = 0; mt < 4; mt++)
        aAddr[mt] = smem_u32(As) + (uint32_t)((wm + mt*16 + rowa) * GSTR + worda) * 4u;
#pragma unroll
    for (int p = 0; p < 2; p++)
        bAddr[p] = smem_u32(Bs) + (uint32_t)((wn + p*16 + rowb) * GSTR + wordb) * 4u;

    float acc[4][4][4];
#pragma unroll
    for (int i = 0; i < 4; i++)
#pragma unroll
        for (int j = 0; j < 4; j++)
#pragma unroll
            for (int r = 0; r < 4; r++) acc[i][j][r] = 0.f;

    const int NIT = GKW / GBK;     // 16

#pragma unroll
    for (int i = 0; i < 4; i++) {
        CP_ASYNC16(sA + i*16, Ag + i*4);
        CP_ASYNC16(sB + i*16, Bg + i*4);
    }
    CP_COMMIT();

    for (int c = 0; c < NIT; c++) {
        int buf = c & 1;
        if (c + 1 < NIT) {
            int nb = buf ^ 1;
#pragma unroll
            for (int i = 0; i < 4; i++) {
                CP_ASYNC16(sA + nb*stageB + i*16, Ag + (c+1)*GBK + i*4);
                CP_ASYNC16(sB + nb*stageB + i*16, Bg + (c+1)*GBK + i*4);
            }
            CP_COMMIT();
            CP_WAIT(1);
        } else {
            CP_WAIT(0);
        }
        __syncthreads();

        uint32_t so = buf * stageB;

#pragma unroll
        for (int kk = 0; kk < 4; kk++) {
            uint32_t ko = so + kk * 32u;
            uint32_t af[4][4], bf[4][2];
#pragma unroll
            for (int mt = 0; mt < 4; mt++)
                ldsm_x4(af[mt][0], af[mt][1], af[mt][2], af[mt][3], aAddr[mt] + ko);
#pragma unroll
            for (int p = 0; p < 2; p++)
                ldsm_x4(bf[2*p][0], bf[2*p][1], bf[2*p+1][0], bf[2*p+1][1], bAddr[p] + ko);
#pragma unroll
            for (int mt = 0; mt < 4; mt++)
#pragma unroll
                for (int nt = 0; nt < 4; nt++)
                    mma_f16(acc[mt][nt][0], acc[mt][nt][1], acc[mt][nt][2], acc[mt][nt][3],
                            af[mt][0], af[mt][1], af[mt][2], af[mt][3],
                            bf[nt][0], bf[nt][1]);
        }
        __syncthreads();
    }

    int baseRow = blockIdx.y * 128 + wm;
    int baseCol = blockIdx.x * 128 + wn;
#pragma unroll
    for (int mt = 0; mt < 4; mt++) {
#pragma unroll
        for (int nt = 0; nt < 4; nt++) {
            int row = baseRow + mt * 16 + gid;
            int col = baseCol + nt * 8 + tig * 2;
            *(float2*)(C + (size_t)row * Np + col)       = make_float2(acc[mt][nt][0], acc[mt][nt][1]);
            *(float2*)(C + (size_t)(row + 8) * Np + col) = make_float2(acc[mt][nt][2], acc[mt][nt][3]);
        }
    }
}

// ---------------- pack: RMSNorm + RoPE (+gain) for q/k only ----------------
__global__ __launch_bounds__(256) void pack_kernel()
{
    int w    = (blockIdx.x * 256 + threadIdx.x) >> 5;
    int lane = threadIdx.x & 31;
    int t    = w / 20;
    int slot = w - t * 20;
    int b = t / SEQ;
    int n = t - b * SEQ;

    float v0, v1;
    float gain;
    __half* dst;

    if (slot < 16) {
        const float* src = g_qkv + (size_t)t * NQKV + slot * HD;
        v0 = src[lane]; v1 = src[lane + 32];
        dst = g_qh + (((size_t)(b * NH + slot)) * SEQ + n) * HD;
        gain = 1.5f * 0.125f * 1.4426950408889634f;   // qk_gain * 1/sqrt(D) * log2(e)
    } else {
        int h = slot - 16;
        const float* src = g_qkv + (size_t)t * NQKV + 1024 + h * HD;
        v0 = src[lane]; v1 = src[lane + 32];
        dst = g_kh + (((size_t)(b * NHKV + h)) * SEQ + n) * HD;
        gain = 1.0f;
    }

    float ss = v0*v0 + v1*v1;
#pragma unroll
    for (int o = 16; o; o >>= 1) ss += __shfl_xor_sync(0xffffffffu, ss, o);
    float r = rsqrtf(ss * (1.0f/64.0f) + 1.1920929e-7f);
    v0 *= r; v1 *= r;
    float inv_freq = powf(10000.0f, -(float)lane * (1.0f/32.0f));
    float ang = (float)n * inv_freq;
    float sv, cv;
    sincosf(ang, &sv, &cv);
    float o0 = v0*cv - v1*sv;
    float o1 = v1*cv + v0*sv;
    dst[lane]      = __float2half(o0 * gain);
    dst[lane + 32] = __float2half(o1 * gain);
}

// ---------------- V transpose: g_qkv v-section -> g_vt [b,h][d][n] ----------
__global__ __launch_bounds__(256) void vtrans_kernel()
{
    __shared__ float t[32][33];
    int z  = blockIdx.z;
    int d0 = blockIdx.y * 32;
    int n0 = blockIdx.x * 32;
    int b  = z >> 2, h = z & 3;
    int tx = threadIdx.x, ty = threadIdx.y;

    const float* src = g_qkv + 1280 + h * HD + d0 + tx;
#pragma unroll
    for (int i = 0; i < 32; i += 8)
        t[ty + i][tx] = src[(size_t)(b*SEQ + n0 + ty + i) * NQKV];
    __syncthreads();

    __half* dst = g_vt + (size_t)z * HD * SEQ + n0 + tx;
#pragma unroll
    for (int i = 0; i < 32; i += 8)
        dst[(size_t)(d0 + ty + i) * SEQ] = __float2half(t[tx][ty + i]);
}

// ---------------- fp16 tensor-core causal flash attention -------------------
// CTA: 128 q-rows, 8 warps x 16 rows, 64-key tiles, 3-stage cp.async ring,
// one __syncthreads per tile, ldmatrix loads, register-direct P,
// FIXED-max softmax in log2 domain (no online max / rescale).
#define ASTR 36
#define QPOFF    (6*64*ASTR)
#define APS(r,wd)    smA[QPOFF    + (r)*ASTR + (wd)]
#define ATTN_SMEM ((6*64 + 128)*ASTR*4)     // 73728 B

__global__ __launch_bounds__(256, 2) void attn_mma_kernel()
{
    extern __shared__ uint32_t smA[];

    int qb = (gridDim.x - 1) - blockIdx.x;   // descending work order
    int h = blockIdx.y, b = blockIdx.z;
    int tid = threadIdx.x;
    int wid = tid >> 5, lane = tid & 31;
    int gid = lane >> 2, tig = lane & 3;
    int r0 = wid * 16;
    int hkv = h >> 2;

    const __half* qbase = g_qh + ((size_t)(b*NH   + h  )) * SEQ * HD;
    const __half* kbase = g_kh + ((size_t)(b*NHKV + hkv)) * SEQ * HD;
    const __half* vtb   = g_vt + ((size_t)(b*NHKV + hkv)) * HD * SEQ;

    int skey  = tid >> 2;
    int squar = tid & 3;

    uint32_t smbase = smem_u32(smA);
    uint32_t kdst0 = smbase + (uint32_t)(skey*ASTR + squar*8) * 4u;
    const uint32_t kstage = (uint32_t)(64*ASTR) * 4u;

    int rowa  = (lane & 7) + ((lane >> 3) & 1) * 8;
    int worda = (lane >> 4) * 4;
    int rowb  = (lane & 7) + ((lane >> 4) << 3);
    int wordb = ((lane >> 3) & 1) * 4;
    uint32_t qAddr = smbase + (uint32_t)(QPOFF + (r0 + rowa)*ASTR + worda) * 4u;
    uint32_t kAddr[4], vAddr[4];
#pragma unroll
    for (int p = 0; p < 4; p++) {
        kAddr[p] = smbase + (uint32_t)((p*16 + rowb)*ASTR + wordb) * 4u;
        vAddr[p] = kAddr[p] + 3*kstage;
    }

    int ntiles = 2*qb + 2;

    // ---- prologue: issue tiles 0 and 1
#pragma unroll
    for (int pt = 0; pt < 2; pt++) {
        if (pt < ntiles) {
            const __half* kr = kbase + (size_t)(pt*64 + skey) * HD + squar*16;
            const __half* vr = vtb + (size_t)skey * SEQ + pt*64 + squar*16;
            CP_ASYNC16(kdst0 + pt*kstage,          kr);
            CP_ASYNC16(kdst0 + pt*kstage + 16,     kr + 8);
            CP_ASYNC16(kdst0 + (3+pt)*kstage,      vr);
            CP_ASYNC16(kdst0 + (3+pt)*kstage + 16, vr + 8);
            CP_COMMIT();
        }
    }

    // ---- stage Q
    {
        int srow  = tid >> 1;
        int shalf = tid & 1;
        const uint4* qr = (const uint4*)(qbase + (size_t)(qb*128 + srow) * HD + shalf*32);
#pragma unroll
        for (int i = 0; i < 4; i++)
            *(uint4*)&APS(srow, shalf*16 + i*4) = qr[i];
    }
    __syncthreads();

    uint32_t qf[4][4];
#pragma unroll
    for (int ks = 0; ks < 4; ks++)
        ldsm_x4(qf[ks][0], qf[ks][1], qf[ks][2], qf[ks][3], qAddr + ks*32u);

    float l0 = 0.f, l1 = 0.f;
    float o[8][4];
#pragma unroll
    for (int nt = 0; nt < 8; nt++)
#pragma unroll
        for (int j = 0; j < 4; j++) o[nt][j] = 0.f;

    int row0 = qb*128 + r0 + gid;
    int row1 = row0 + 8;
    int rowmax = qb*128 + r0 + 15;

    int buf = 0;
    for (int kt = 0; kt < ntiles; kt++, buf = (buf == 2 ? 0 : buf + 1)) {
        int k0 = kt * 64;

        if (kt < ntiles - 1) CP_WAIT(1); else CP_WAIT(0);
        __syncthreads();

        if (kt + 2 < ntiles) {
            int nb = buf + 2; if (nb >= 3) nb -= 3;
            int nk0 = k0 + 128;
            const __half* kr = kbase + (size_t)(nk0 + skey) * HD + squar*16;
            const __half* vr = vtb + (size_t)skey * SEQ + nk0 + squar*16;
            CP_ASYNC16(kdst0 + nb*kstage,          kr);
            CP_ASYNC16(kdst0 + nb*kstage + 16,     kr + 8);
            CP_ASYNC16(kdst0 + (3+nb)*kstage,      vr);
            CP_ASYNC16(kdst0 + (3+nb)*kstage + 16, vr + 8);
            CP_COMMIT();
        }

        if (k0 > rowmax) continue;

        uint32_t bo = buf * kstage;

        // ---- scores S' = (Q*log2e) @ K^T  (log2 domain)
        float s[8][4];
#pragma unroll
        for (int nt = 0; nt < 8; nt++)
#pragma unroll
            for (int j = 0; j < 4; j++) s[nt][j] = 0.f;

#pragma unroll
        for (int ks = 0; ks < 4; ks++) {
            uint32_t ko = bo + ks*32u;
#pragma unroll
            for (int p = 0; p < 4; p++) {
                uint32_t b00, b01, b10, b11;
                ldsm_x4(b00, b01, b10, b11, kAddr[p] + ko);
                mma_f16(s[2*p][0], s[2*p][1], s[2*p][2], s[2*p][3],
                        qf[ks][0], qf[ks][1], qf[ks][2], qf[ks][3], b00, b01);
                mma_f16(s[2*p+1][0], s[2*p+1][1], s[2*p+1][2], s[2*p+1][3],
                        qf[ks][0], qf[ks][1], qf[ks][2], qf[ks][3], b10, b11);
            }
        }

        if (k0 + 63 > row0) {
#pragma unroll
            for (int nt = 0; nt < 8; nt++) {
                int key = k0 + nt*8 + 2*tig;
                if (key     > row0) s[nt][0] = -1e30f;
                if (key + 1 > row0) s[nt][1] = -1e30f;
                if (key     > row1) s[nt][2] = -1e30f;
                if (key + 1 > row1) s[nt][3] = -1e30f;
            }
        }

        // ---- fixed-max softmax: p = 2^(s' - 6*log2e)
#pragma unroll
        for (int nt = 0; nt < 8; nt++) {
            s[nt][0] = ex2f(s[nt][0] - FMAXL2);
            s[nt][1] = ex2f(s[nt][1] - FMAXL2);
            s[nt][2] = ex2f(s[nt][2] - FMAXL2);
            s[nt][3] = ex2f(s[nt][3] - FMAXL2);
            l0 += s[nt][0] + s[nt][1];
            l1 += s[nt][2] + s[nt][3];
        }

        // ---- O += P @ V  (P A-fragments built directly from score registers)
#pragma unroll
        for (int ks = 0; ks < 4; ks++) {
            uint32_t a0 = f2h2(s[2*ks  ][0], s[2*ks  ][1]);
            uint32_t a1 = f2h2(s[2*ks  ][2], s[2*ks  ][3]);
            uint32_t a2 = f2h2(s[2*ks+1][0], s[2*ks+1][1]);
            uint32_t a3 = f2h2(s[2*ks+1][2], s[2*ks+1][3]);
            uint32_t ko = bo + ks*32u;
#pragma unroll
            for (int p = 0; p < 4; p++) {
                uint32_t b00, b01, b10, b11;
                ldsm_x4(b00, b01, b10, b11, vAddr[p] + ko);
                mma_f16(o[2*p][0], o[2*p][1], o[2*p][2], o[2*p][3],
                        a0, a1, a2, a3, b00, b01);
                mma_f16(o[2*p+1][0], o[2*p+1][1], o[2*p+1][2], o[2*p+1][3],
                        a0, a1, a2, a3, b10, b11);
            }
        }
    }

    // ---- single end-of-kernel l reduction across the quad
    l0 += __shfl_xor_sync(0xffffffffu, l0, 1);
    l0 += __shfl_xor_sync(0xffffffffu, l0, 2);
    l1 += __shfl_xor_sync(0xffffffffu, l1, 1);
    l1 += __shfl_xor_sync(0xffffffffu, l1, 2);

    float i0 = 1.0f / l0, i1 = 1.0f / l1;
    uint32_t* y0 = g_y + (((size_t)(b*SEQ + row0)) * NH + h) * (HD/2);
    uint32_t* y1 = g_y + (((size_t)(b*SEQ + row1)) * NH + h) * (HD/2);
#pragma unroll
    for (int nt = 0; nt < 8; nt++) {
        y0[nt*4+tig] = f2h2(o[nt][0] * i0, o[nt][1] * i0);
        y1[nt*4+tig] = f2h2(o[nt][2] * i1, o[nt][3] * i1);
    }
}

// ---------------- launch ----------------------------------------------------
extern "C" void kernel_launch(void* const* d_in, const int* in_sizes, int n_in,
                              void* d_out, int out_size)
{
    const float* x  = (const float*)d_in[0];
    const float* wq = (const float*)d_in[1];
    const float* wk = (const float*)d_in[2];
    const float* wv = (const float*)d_in[3];
    const float* wo = (const float*)d_in[4];
    float* out = (float*)d_out;

    uint32_t *xh, *wqkvT, *woT, *yy;
    float *qkv;
    cudaGetSymbolAddress((void**)&xh,    g_xh);
    cudaGetSymbolAddress((void**)&qkv,   g_qkv);
    cudaGetSymbolAddress((void**)&wqkvT, g_wqkvT);
    cudaGetSymbolAddress((void**)&woT,   g_woT);
    cudaGetSymbolAddress((void**)&yy,    g_y);

    static bool init_done = false;
    static cudaStream_t s1;
    static cudaEvent_t e_fork, e_wt, e_wo, e_g1, e_vt;
    if (!init_done) {
        cudaStreamCreateWithFlags(&s1, cudaStreamNonBlocking);
        cudaEventCreateWithFlags(&e_fork, cudaEventDisableTiming);
        cudaEventCreateWithFlags(&e_wt,   cudaEventDisableTiming);
        cudaEventCreateWithFlags(&e_wo,   cudaEventDisableTiming);
        cudaEventCreateWithFlags(&e_g1,   cudaEventDisableTiming);
        cudaEventCreateWithFlags(&e_vt,   cudaEventDisableTiming);
        cudaFuncSetAttribute(mma_gemm_kernel, cudaFuncAttributeMaxDynamicSharedMemorySize, GEMM_SMEM);
        cudaFuncSetAttribute(attn_mma_kernel, cudaFuncAttributeMaxDynamicSharedMemorySize, ATTN_SMEM);
        init_done = true;
    }

    cudaEventRecord(e_fork, 0);
    cudaStreamWaitEvent(s1, e_fork, 0);

    xconv_kernel<<<TOK*CDIM/(256*4), 256>>>(x);

    transpose_kernel<<<dim3(32,32), dim3(32,8), 0, s1>>>(wq, (__half*)wqkvT,               CDIM, CDIM);
    transpose_kernel<<<dim3(8, 32), dim3(32,8), 0, s1>>>(wk, (__half*)(wqkvT + 1024*GKW),  CDIM, NHKV*HD);
    transpose_kernel<<<dim3(8, 32), dim3(32,8), 0, s1>>>(wv, (__half*)(wqkvT + 1280*GKW),  CDIM, NHKV*HD);
    cudaEventRecord(e_wt, s1);
    transpose_kernel<<<dim3(32,32), dim3(32,8), 0, s1>>>(wo, (__half*)woT,                 CDIM, CDIM);
    cudaEventRecord(e_wo, s1);

    cudaStreamWaitEvent(0, e_wt, 0);

    // fused QKV projection (fp32 output)
    mma_gemm_kernel<<<dim3(NQKV/128, TOK/128), 256, GEMM_SMEM>>>(xh, wqkvT, qkv, NQKV);
    cudaEventRecord(e_g1, 0);

    // vtrans on side stream overlaps pack on main stream
    cudaStreamWaitEvent(s1, e_g1, 0);
    vtrans_kernel<<<dim3(SEQ/32, HD/32, BATCH*NHKV), dim3(32,8), 0, s1>>>();
    cudaEventRecord(e_vt, s1);

    pack_kernel<<<(TOK*20)/8, 256>>>();
    cudaStreamWaitEvent(0, e_vt, 0);

    attn_mma_kernel<<<dim3(SEQ/128, NH, BATCH), 256, ATTN_SMEM>>>();

    cudaStreamWaitEvent(0, e_wo, 0);
    mma_gemm_kernel<<<dim3(CDIM/128, TOK/128), 256, GEMM_SMEM>>>(yy, woT, out, CDIM);
}

// round 14
// speedup vs baseline: 1.7159x; 1.7159x over previous
#include <cuda_runtime.h>
#include <cuda_fp16.h>
#include <math.h>
#include <stdint.h>

// ---------------- problem constants ----------------
#define BATCH 4
#define SEQ   2048
#define CDIM  1024
#define NH    16
#define NHKV  4
#define HD    64
#define TOK   (BATCH*SEQ)          // 8192
#define GKW   512                  // K dim in half2 words (1024 halves)
#define NQKV  1536                 // 1024 + 256 + 256

// ---------------- scratch (device globals) ----------------
__device__ uint32_t g_xh  [TOK*GKW];         // x as half2 words
__device__ float    g_qkv [TOK*NQKV];        // fused qkv projection (fp32)
__device__ __half   g_qh [BATCH*NH*SEQ*HD];  // q half, scale folded (1.5/8*log2e)
__device__ __half   g_kh [BATCH*NHKV*SEQ*HD];// k half [b,hkv][n][d]
__device__ __half   g_vt [BATCH*NHKV*HD*SEQ];// v half transposed [b,hkv][d][n]
__device__ uint32_t g_y  [TOK*GKW];          // attention out, half2 words
__device__ uint32_t g_wqkvT[NQKV*GKW];       // [N,K] transposed weights half2
__device__ uint32_t g_woT  [CDIM*GKW];

// ---------------- helpers ----------------
__device__ __forceinline__ uint32_t smem_u32(const void* p) {
    uint32_t a;
    asm("{ .reg .u64 t; cvta.to.shared.u64 t, %1; cvt.u32.u64 %0, t; }" : "=r"(a) : "l"(p));
    return a;
}
__device__ __forceinline__ uint32_t f2h2(float lo, float hi) {
    __half2 h = __floats2half2_rn(lo, hi);
    return *(uint32_t*)&h;
}
__device__ __forceinline__ float ex2f(float x) {
    float y;
    asm("ex2.approx.f32 %0, %1;" : "=f"(y) : "f"(x));
    return y;
}
__device__ __forceinline__ void mma_f16(float& d0, float& d1, float& d2, float& d3,
                                        uint32_t a0, uint32_t a1, uint32_t a2, uint32_t a3,
                                        uint32_t b0, uint32_t b1) {
    asm volatile(
        "mma.sync.aligned.m16n8k16.row.col.f32.f16.f16.f32 "
        "{%0,%1,%2,%3}, {%4,%5,%6,%7}, {%8,%9}, {%0,%1,%2,%3};"
        : "+f"(d0), "+f"(d1), "+f"(d2), "+f"(d3)
        : "r"(a0), "r"(a1), "r"(a2), "r"(a3), "r"(b0), "r"(b1));
}
__device__ __forceinline__ void ldsm_x4(uint32_t& r0, uint32_t& r1, uint32_t& r2, uint32_t& r3,
                                        uint32_t addr) {
    asm volatile("ldmatrix.sync.aligned.m8n8.x4.shared.b16 {%0,%1,%2,%3}, [%4];"
                 : "=r"(r0), "=r"(r1), "=r"(r2), "=r"(r3) : "r"(addr));
}
#define CP_ASYNC16(saddr, gptr) \
    asm volatile("cp.async.cg.shared.global [%0], [%1], 16;" :: "r"(saddr), "l"(gptr))
#define CP_COMMIT()  asm volatile("cp.async.commit_group;" ::: "memory")
#define CP_WAIT(n)   asm volatile("cp.async.wait_group %0;" :: "n"(n) : "memory")

// ---------------- x -> half2 words -----------------------------------------
__global__ __launch_bounds__(256) void xconv_kernel(const float* __restrict__ x)
{
    int i = (blockIdx.x * 256 + threadIdx.x) * 4;
    float4 f = *(const float4*)(x + i);
    uint2 u;
    u.x = f2h2(f.x, f.y);
    u.y = f2h2(f.z, f.w);
    *(uint2*)(g_xh + i/2) = u;
}

// ---------------- weight transpose (+half): D[c][r] = h(S[r][c]) -----------
__global__ __launch_bounds__(256) void transpose_kernel(
    const float* __restrict__ S, __half* __restrict__ D, int R, int Ccols)
{
    __shared__ float t[32][33];
    int bx = blockIdx.x * 32, by = blockIdx.y * 32;
#pragma unroll
    for (int i = 0; i < 32; i += 8)
        t[threadIdx.y + i][threadIdx.x] = S[(size_t)(by + threadIdx.y + i) * Ccols + bx + threadIdx.x];
    __syncthreads();
#pragma unroll
    for (int i = 0; i < 32; i += 8)
        D[(size_t)(bx + threadIdx.y + i) * R + by + threadIdx.x] = __float2half(t[threadIdx.x][threadIdx.y + i]);
}

// ---------------- fp16 GEMM, 2-stage double buffer, ldmatrix fragments ------
#define GS   2
#define GBK  32
#define GSTR 36
#define STAGE_W (128*GSTR)
#define GEMM_SMEM (2*GS*STAGE_W*4)     // 73728 B

__global__ __launch_bounds__(256, 2) void mma_gemm_kernel(
    const uint32_t* __restrict__ A, const uint32_t* __restrict__ Bt,
    float* __restrict__ C, int Np)
{
    extern __shared__ uint32_t gsm[];
    uint32_t* As = gsm;
    uint32_t* Bs = gsm + GS*STAGE_W;

    int tid  = threadIdx.x;
    int wid  = tid >> 5, lane = tid & 31;
    int gid  = lane >> 2, tig = lane & 3;
    int wm   = (wid & 1) * 64;
    int wn   = (wid >> 1) * 32;

    int lr = tid >> 1;
    int lc = (tid & 1) * 16;

    const uint32_t* Ag = A  + (size_t)blockIdx.y * 128 * GKW + (size_t)lr * GKW + lc;
    const uint32_t* Bg = Bt + (size_t)blockIdx.x * 128 * GKW + (size_t)lr * GKW + lc;

    uint32_t sA = smem_u32(As) + (uint32_t)(lr * GSTR + lc) * 4u;
    uint32_t sB = smem_u32(Bs) + (uint32_t)(lr * GSTR + lc) * 4u;
    const uint32_t stageB = STAGE_W * 4u;

    int rowa  = (lane & 7) + ((lane >> 3) & 1) * 8;
    int worda = (lane >> 4) * 4;
    int rowb  = (lane & 7) + ((lane >> 4) << 3);
    int wordb = ((lane >> 3) & 1) * 4;
    uint32_t aAddr[4], bAddr[2];
#pragma unroll
    for (int mt = 0; mt < 4; mt++)
        aAddr[mt] = smem_u32(As) + (uint32_t)((wm + mt*16 + rowa) * GSTR + worda) * 4u;
#pragma unroll
    for (int p = 0; p < 2; p++)
        bAddr[p] = smem_u32(Bs) + (uint32_t)((wn + p*16 + rowb) * GSTR + wordb) * 4u;

    float acc[4][4][4];
#pragma unroll
    for (int i = 0; i < 4; i++)
#pragma unroll
        for (int j = 0; j < 4; j++)
#pragma unroll
            for (int r = 0; r < 4; r++) acc[i][j][r] = 0.f;

    const int NIT = GKW / GBK;     // 16

#pragma unroll
    for (int i = 0; i < 4; i++) {
        CP_ASYNC16(sA + i*16, Ag + i*4);
        CP_ASYNC16(sB + i*16, Bg + i*4);
    }
    CP_COMMIT();

    for (int c = 0; c < NIT; c++) {
        int buf = c & 1;
        if (c + 1 < NIT) {
            int nb = buf ^ 1;
#pragma unroll
            for (int i = 0; i < 4; i++) {
                CP_ASYNC16(sA + nb*stageB + i*16, Ag + (c+1)*GBK + i*4);
                CP_ASYNC16(sB + nb*stageB + i*16, Bg + (c+1)*GBK + i*4);
            }
            CP_COMMIT();
            CP_WAIT(1);
        } else {
            CP_WAIT(0);
        }
        __syncthreads();

        uint32_t so = buf * stageB;

#pragma unroll
        for (int kk = 0; kk < 4; kk++) {
            uint32_t ko = so + kk * 32u;
            uint32_t af[4][4], bf[4][2];
#pragma unroll
            for (int mt = 0; mt < 4; mt++)
                ldsm_x4(af[mt][0], af[mt][1], af[mt][2], af[mt][3], aAddr[mt] + ko);
#pragma unroll
            for (int p = 0; p < 2; p++)
                ldsm_x4(bf[2*p][0], bf[2*p][1], bf[2*p+1][0], bf[2*p+1][1], bAddr[p] + ko);
#pragma unroll
            for (int mt = 0; mt < 4; mt++)
#pragma unroll
                for (int nt = 0; nt < 4; nt++)
                    mma_f16(acc[mt][nt][0], acc[mt][nt][1], acc[mt][nt][2], acc[mt][nt][3],
                            af[mt][0], af[mt][1], af[mt][2], af[mt][3],
                            bf[nt][0], bf[nt][1]);
        }
        __syncthreads();
    }

    int baseRow = blockIdx.y * 128 + wm;
    int baseCol = blockIdx.x * 128 + wn;
#pragma unroll
    for (int mt = 0; mt < 4; mt++) {
#pragma unroll
        for (int nt = 0; nt < 4; nt++) {
            int row = baseRow + mt * 16 + gid;
            int col = baseCol + nt * 8 + tig * 2;
            *(float2*)(C + (size_t)row * Np + col)       = make_float2(acc[mt][nt][0], acc[mt][nt][1]);
            *(float2*)(C + (size_t)(row + 8) * Np + col) = make_float2(acc[mt][nt][2], acc[mt][nt][3]);
        }
    }
}

// ---------------- pack: RMSNorm + RoPE (+gain) for q/k only ----------------
__global__ __launch_bounds__(256) void pack_kernel()
{
    int w    = (blockIdx.x * 256 + threadIdx.x) >> 5;
    int lane = threadIdx.x & 31;
    int t    = w / 20;
    int slot = w - t * 20;
    int b = t / SEQ;
    int n = t - b * SEQ;

    float v0, v1;
    float gain;
    __half* dst;

    if (slot < 16) {
        const float* src = g_qkv + (size_t)t * NQKV + slot * HD;
        v0 = src[lane]; v1 = src[lane + 32];
        dst = g_qh + (((size_t)(b * NH + slot)) * SEQ + n) * HD;
        gain = 1.5f * 0.125f * 1.4426950408889634f;   // qk_gain * 1/sqrt(D) * log2(e)
    } else {
        int h = slot - 16;
        const float* src = g_qkv + (size_t)t * NQKV + 1024 + h * HD;
        v0 = src[lane]; v1 = src[lane + 32];
        dst = g_kh + (((size_t)(b * NHKV + h)) * SEQ + n) * HD;
        gain = 1.0f;
    }

    float ss = v0*v0 + v1*v1;
#pragma unroll
    for (int o = 16; o; o >>= 1) ss += __shfl_xor_sync(0xffffffffu, ss, o);
    float r = rsqrtf(ss * (1.0f/64.0f) + 1.1920929e-7f);
    v0 *= r; v1 *= r;
    float inv_freq = powf(10000.0f, -(float)lane * (1.0f/32.0f));
    float ang = (float)n * inv_freq;
    float sv, cv;
    sincosf(ang, &sv, &cv);
    float o0 = v0*cv - v1*sv;
    float o1 = v1*cv + v0*sv;
    dst[lane]      = __float2half(o0 * gain);
    dst[lane + 32] = __float2half(o1 * gain);
}

// ---------------- V transpose: g_qkv v-section -> g_vt [b,h][d][n] ----------
__global__ __launch_bounds__(256) void vtrans_kernel()
{
    __shared__ float t[32][33];
    int z  = blockIdx.z;
    int d0 = blockIdx.y * 32;
    int n0 = blockIdx.x * 32;
    int b  = z >> 2, h = z & 3;
    int tx = threadIdx.x, ty = threadIdx.y;

    const float* src = g_qkv + 1280 + h * HD + d0 + tx;
#pragma unroll
    for (int i = 0; i < 32; i += 8)
        t[ty + i][tx] = src[(size_t)(b*SEQ + n0 + ty + i) * NQKV];
    __syncthreads();

    __half* dst = g_vt + (size_t)z * HD * SEQ + n0 + tx;
#pragma unroll
    for (int i = 0; i < 32; i += 8)
        dst[(size_t)(d0 + ty + i) * SEQ] = __float2half(t[tx][ty + i]);
}

// ---------------- fp16 tensor-core causal flash attention -------------------
// CTA: 128 q-rows, 8 warps x 16 rows, 64-key tiles, 3-stage cp.async ring,
// one __syncthreads per tile, ldmatrix loads, register-direct P,
// ONLINE-max softmax in log2 domain (q pre-scaled by log2e).
#define ASTR 36
#define QPOFF    (6*64*ASTR)
#define APS(r,wd)    smA[QPOFF    + (r)*ASTR + (wd)]
#define ATTN_SMEM ((6*64 + 128)*ASTR*4)     // 73728 B

__global__ __launch_bounds__(256, 2) void attn_mma_kernel()
{
    extern __shared__ uint32_t smA[];

    int qb = (gridDim.x - 1) - blockIdx.x;   // descending work order
    int h = blockIdx.y, b = blockIdx.z;
    int tid = threadIdx.x;
    int wid = tid >> 5, lane = tid & 31;
    int gid = lane >> 2, tig = lane & 3;
    int r0 = wid * 16;
    int hkv = h >> 2;

    const __half* qbase = g_qh + ((size_t)(b*NH   + h  )) * SEQ * HD;
    const __half* kbase = g_kh + ((size_t)(b*NHKV + hkv)) * SEQ * HD;
    const __half* vtb   = g_vt + ((size_t)(b*NHKV + hkv)) * HD * SEQ;

    int skey  = tid >> 2;
    int squar = tid & 3;

    uint32_t smbase = smem_u32(smA);
    uint32_t kdst0 = smbase + (uint32_t)(skey*ASTR + squar*8) * 4u;
    const uint32_t kstage = (uint32_t)(64*ASTR) * 4u;

    int rowa  = (lane & 7) + ((lane >> 3) & 1) * 8;
    int worda = (lane >> 4) * 4;
    int rowb  = (lane & 7) + ((lane >> 4) << 3);
    int wordb = ((lane >> 3) & 1) * 4;
    uint32_t qAddr = smbase + (uint32_t)(QPOFF + (r0 + rowa)*ASTR + worda) * 4u;
    uint32_t kAddr[4], vAddr[4];
#pragma unroll
    for (int p = 0; p < 4; p++) {
        kAddr[p] = smbase + (uint32_t)((p*16 + rowb)*ASTR + wordb) * 4u;
        vAddr[p] = kAddr[p] + 3*kstage;
    }

    int ntiles = 2*qb + 2;

    // ---- prologue: issue tiles 0 and 1
#pragma unroll
    for (int pt = 0; pt < 2; pt++) {
        if (pt < ntiles) {
            const __half* kr = kbase + (size_t)(pt*64 + skey) * HD + squar*16;
            const __half* vr = vtb + (size_t)skey * SEQ + pt*64 + squar*16;
            CP_ASYNC16(kdst0 + pt*kstage,          kr);
            CP_ASYNC16(kdst0 + pt*kstage + 16,     kr + 8);
            CP_ASYNC16(kdst0 + (3+pt)*kstage,      vr);
            CP_ASYNC16(kdst0 + (3+pt)*kstage + 16, vr + 8);
            CP_COMMIT();
        }
    }

    // ---- stage Q
    {
        int srow  = tid >> 1;
        int shalf = tid & 1;
        const uint4* qr = (const uint4*)(qbase + (size_t)(qb*128 + srow) * HD + shalf*32);
#pragma unroll
        for (int i = 0; i < 4; i++)
            *(uint4*)&APS(srow, shalf*16 + i*4) = qr[i];
    }
    __syncthreads();

    uint32_t qf[4][4];
#pragma unroll
    for (int ks = 0; ks < 4; ks++)
        ldsm_x4(qf[ks][0], qf[ks][1], qf[ks][2], qf[ks][3], qAddr + ks*32u);

    float m0 = -1e30f, m1 = -1e30f, l0 = 0.f, l1 = 0.f;
    float o[8][4];
#pragma unroll
    for (int nt = 0; nt < 8; nt++)
#pragma unroll
        for (int j = 0; j < 4; j++) o[nt][j] = 0.f;

    int row0 = qb*128 + r0 + gid;
    int row1 = row0 + 8;
    int rowmax = qb*128 + r0 + 15;

    int buf = 0;
    for (int kt = 0; kt < ntiles; kt++, buf = (buf == 2 ? 0 : buf + 1)) {
        int k0 = kt * 64;

        if (kt < ntiles - 1) CP_WAIT(1); else CP_WAIT(0);
        __syncthreads();

        if (kt + 2 < ntiles) {
            int nb = buf + 2; if (nb >= 3) nb -= 3;
            int nk0 = k0 + 128;
            const __half* kr = kbase + (size_t)(nk0 + skey) * HD + squar*16;
            const __half* vr = vtb + (size_t)skey * SEQ + nk0 + squar*16;
            CP_ASYNC16(kdst0 + nb*kstage,          kr);
            CP_ASYNC16(kdst0 + nb*kstage + 16,     kr + 8);
            CP_ASYNC16(kdst0 + (3+nb)*kstage,      vr);
            CP_ASYNC16(kdst0 + (3+nb)*kstage + 16, vr + 8);
            CP_COMMIT();
        }

        if (k0 > rowmax) continue;

        uint32_t bo = buf * kstage;

        // ---- scores S' = (Q*log2e) @ K^T  (log2 domain)
        float s[8][4];
#pragma unroll
        for (int nt = 0; nt < 8; nt++)
#pragma unroll
            for (int j = 0; j < 4; j++) s[nt][j] = 0.f;

#pragma unroll
        for (int ks = 0; ks < 4; ks++) {
            uint32_t ko = bo + ks*32u;
#pragma unroll
            for (int p = 0; p < 4; p++) {
                uint32_t b00, b01, b10, b11;
                ldsm_x4(b00, b01, b10, b11, kAddr[p] + ko);
                mma_f16(s[2*p][0], s[2*p][1], s[2*p][2], s[2*p][3],
                        qf[ks][0], qf[ks][1], qf[ks][2], qf[ks][3], b00, b01);
                mma_f16(s[2*p+1][0], s[2*p+1][1], s[2*p+1][2], s[2*p+1][3],
                        qf[ks][0], qf[ks][1], qf[ks][2], qf[ks][3], b10, b11);
            }
        }

        if (k0 + 63 > row0) {
#pragma unroll
            for (int nt = 0; nt < 8; nt++) {
                int key = k0 + nt*8 + 2*tig;
                if (key     > row0) s[nt][0] = -1e30f;
                if (key + 1 > row0) s[nt][1] = -1e30f;
                if (key     > row1) s[nt][2] = -1e30f;
                if (key + 1 > row1) s[nt][3] = -1e30f;
            }
        }

        // ---- online softmax (log2 domain)
        float mx0 = m0, mx1 = m1;
#pragma unroll
        for (int nt = 0; nt < 8; nt++) {
            mx0 = fmaxf(mx0, fmaxf(s[nt][0], s[nt][1]));
            mx1 = fmaxf(mx1, fmaxf(s[nt][2], s[nt][3]));
        }
        mx0 = fmaxf(mx0, __shfl_xor_sync(0xffffffffu, mx0, 1));
        mx0 = fmaxf(mx0, __shfl_xor_sync(0xffffffffu, mx0, 2));
        mx1 = fmaxf(mx1, __shfl_xor_sync(0xffffffffu, mx1, 1));
        mx1 = fmaxf(mx1, __shfl_xor_sync(0xffffffffu, mx1, 2));

        float c0 = ex2f(m0 - mx0);
        float c1 = ex2f(m1 - mx1);
        m0 = mx0; m1 = mx1;
        l0 *= c0;  l1 *= c1;
#pragma unroll
        for (int nt = 0; nt < 8; nt++) {
            o[nt][0] *= c0; o[nt][1] *= c0;
            o[nt][2] *= c1; o[nt][3] *= c1;
        }

        float ps0 = 0.f, ps1 = 0.f;
#pragma unroll
        for (int nt = 0; nt < 8; nt++) {
            s[nt][0] = ex2f(s[nt][0] - mx0);
            s[nt][1] = ex2f(s[nt][1] - mx0);
            s[nt][2] = ex2f(s[nt][2] - mx1);
            s[nt][3] = ex2f(s[nt][3] - mx1);
            ps0 += s[nt][0] + s[nt][1];
            ps1 += s[nt][2] + s[nt][3];
        }
        ps0 += __shfl_xor_sync(0xffffffffu, ps0, 1);
        ps0 += __shfl_xor_sync(0xffffffffu, ps0, 2);
        ps1 += __shfl_xor_sync(0xffffffffu, ps1, 1);
        ps1 += __shfl_xor_sync(0xffffffffu, ps1, 2);
        l0 += ps0; l1 += ps1;

        // ---- O += P @ V  (P A-fragments built directly from score registers)
#pragma unroll
        for (int ks = 0; ks < 4; ks++) {
            uint32_t a0 = f2h2(s[2*ks  ][0], s[2*ks  ][1]);
            uint32_t a1 = f2h2(s[2*ks  ][2], s[2*ks  ][3]);
            uint32_t a2 = f2h2(s[2*ks+1][0], s[2*ks+1][1]);
            uint32_t a3 = f2h2(s[2*ks+1][2], s[2*ks+1][3]);
            uint32_t ko = bo + ks*32u;
#pragma unroll
            for (int p = 0; p < 4; p++) {
                uint32_t b00, b01, b10, b11;
                ldsm_x4(b00, b01, b10, b11, vAddr[p] + ko);
                mma_f16(o[2*p][0], o[2*p][1], o[2*p][2], o[2*p][3],
                        a0, a1, a2, a3, b00, b01);
                mma_f16(o[2*p+1][0], o[2*p+1][1], o[2*p+1][2], o[2*p+1][3],
                        a0, a1, a2, a3, b10, b11);
            }
        }
    }

    float i0 = 1.0f / l0, i1 = 1.0f / l1;
    uint32_t* y0 = g_y + (((size_t)(b*SEQ + row0)) * NH + h) * (HD/2);
    uint32_t* y1 = g_y + (((size_t)(b*SEQ + row1)) * NH + h) * (HD/2);
#pragma unroll
    for (int nt = 0; nt < 8; nt++) {
        y0[nt*4+tig] = f2h2(o[nt][0] * i0, o[nt][1] * i0);
        y1[nt*4+tig] = f2h2(o[nt][2] * i1, o[nt][3] * i1);
    }
}

// ---------------- launch ----------------------------------------------------
extern "C" void kernel_launch(void* const* d_in, const int* in_sizes, int n_in,
                              void* d_out, int out_size)
{
    const float* x  = (const float*)d_in[0];
    const float* wq = (const float*)d_in[1];
    const float* wk = (const float*)d_in[2];
    const float* wv = (const float*)d_in[3];
    const float* wo = (const float*)d_in[4];
    float* out = (float*)d_out;

    uint32_t *xh, *wqkvT, *woT, *yy;
    float *qkv;
    cudaGetSymbolAddress((void**)&xh,    g_xh);
    cudaGetSymbolAddress((void**)&qkv,   g_qkv);
    cudaGetSymbolAddress((void**)&wqkvT, g_wqkvT);
    cudaGetSymbolAddress((void**)&woT,   g_woT);
    cudaGetSymbolAddress((void**)&yy,    g_y);

    static bool init_done = false;
    static cudaStream_t s1;
    static cudaEvent_t e_fork, e_wt, e_wo, e_g1, e_vt;
    if (!init_done) {
        cudaStreamCreateWithFlags(&s1, cudaStreamNonBlocking);
        cudaEventCreateWithFlags(&e_fork, cudaEventDisableTiming);
        cudaEventCreateWithFlags(&e_wt,   cudaEventDisableTiming);
        cudaEventCreateWithFlags(&e_wo,   cudaEventDisableTiming);
        cudaEventCreateWithFlags(&e_g1,   cudaEventDisableTiming);
        cudaEventCreateWithFlags(&e_vt,   cudaEventDisableTiming);
        cudaFuncSetAttribute(mma_gemm_kernel, cudaFuncAttributeMaxDynamicSharedMemorySize, GEMM_SMEM);
        cudaFuncSetAttribute(attn_mma_kernel, cudaFuncAttributeMaxDynamicSharedMemorySize, ATTN_SMEM);
        init_done = true;
    }

    cudaEventRecord(e_fork, 0);
    cudaStreamWaitEvent(s1, e_fork, 0);

    xconv_kernel<<<TOK*CDIM/(256*4), 256>>>(x);

    transpose_kernel<<<dim3(32,32), dim3(32,8), 0, s1>>>(wq, (__half*)wqkvT,               CDIM, CDIM);
    transpose_kernel<<<dim3(8, 32), dim3(32,8), 0, s1>>>(wk, (__half*)(wqkvT + 1024*GKW),  CDIM, NHKV*HD);
    transpose_kernel<<<dim3(8, 32), dim3(32,8), 0, s1>>>(wv, (__half*)(wqkvT + 1280*GKW),  CDIM, NHKV*HD);
    cudaEventRecord(e_wt, s1);
    transpose_kernel<<<dim3(32,32), dim3(32,8), 0, s1>>>(wo, (__half*)woT,                 CDIM, CDIM);
    cudaEventRecord(e_wo, s1);

    cudaStreamWaitEvent(0, e_wt, 0);

    // fused QKV projection (fp32 output)
    mma_gemm_kernel<<<dim3(NQKV/128, TOK/128), 256, GEMM_SMEM>>>(xh, wqkvT, qkv, NQKV);
    cudaEventRecord(e_g1, 0);

    // vtrans on side stream overlaps pack on main stream
    cudaStreamWaitEvent(s1, e_g1, 0);
    vtrans_kernel<<<dim3(SEQ/32, HD/32, BATCH*NHKV), dim3(32,8), 0, s1>>>();
    cudaEventRecord(e_vt, s1);

    pack_kernel<<<(TOK*20)/8, 256>>>();
    cudaStreamWaitEvent(0, e_vt, 0);

    attn_mma_kernel<<<dim3(SEQ/128, NH, BATCH), 256, ATTN_SMEM>>>();

    cudaStreamWaitEvent(0, e_wo, 0);
    mma_gemm_kernel<<<dim3(CDIM/128, TOK/128), 256, GEMM_SMEM>>>(yy, woT, out, CDIM);
}